// round 3
// baseline (speedup 1.0000x reference)
#include <cuda_runtime.h>
#include <math.h>
#include <stdint.h>

#define EMB   768
#define NHEAD 12
#define HDIM  64
#define SEQ   1024
#define BATCH 8
#define MTOT  (BATCH * SEQ)
#define FQKV  (3 * EMB)
#define BHTOT (BATCH * NHEAD)

__device__ float g_qkv[(size_t)MTOT * FQKV];   // 75.5 MB
__device__ float g_oh [(size_t)MTOT * EMB];    // 25.2 MB

__device__ __forceinline__ uint32_t f2tf(float x) {
    uint32_t r;
    asm("cvt.rna.tf32.f32 %0, %1;" : "=r"(r) : "f"(x));
    return r;
}

__device__ __forceinline__ void mma8(float* c,
                                     uint32_t a0, uint32_t a1, uint32_t a2, uint32_t a3,
                                     uint32_t b0, uint32_t b1)
{
    asm volatile(
        "mma.sync.aligned.m16n8k8.row.col.f32.tf32.tf32.f32 "
        "{%0,%1,%2,%3}, {%4,%5,%6,%7}, {%8,%9}, {%0,%1,%2,%3};\n"
        : "+f"(c[0]), "+f"(c[1]), "+f"(c[2]), "+f"(c[3])
        : "r"(a0), "r"(a1), "r"(a2), "r"(a3), "r"(b0), "r"(b1));
}

// ===========================================================================
// Weight GEMM (C = A * B^T [+bias]).  Block 128x64, 256 thr, tf32 converted
// at smem-store time (hi/lo for SPLIT). Dynamic smem.
// ===========================================================================
template<bool SPLIT>
__device__ __forceinline__ void gemm_v2(
    const float* __restrict__ A, int lda,
    const float* __restrict__ B, int ldb,
    float*       __restrict__ C, int ldc,
    int row0, int col0, int K,
    const float* __restrict__ bias)
{
    extern __shared__ uint32_t smu[];
    uint32_t* Ah = smu;                                   // 128*36
    uint32_t* Al = SPLIT ? Ah + 128 * 36 : (uint32_t*)0;
    uint32_t* Bh = Ah + (SPLIT ? 2 : 1) * 128 * 36;       // 64*36
    uint32_t* Bl = SPLIT ? Bh + 64 * 36 : (uint32_t*)0;

    const int t = threadIdx.x, warp = t >> 5, lane = t & 31;
    const int wm = warp >> 2, wn = warp & 3;
    const int g = lane >> 2, tg = lane & 3;

    float acc[4][2][4] = {};

    for (int k0 = 0; k0 < K; k0 += 32) {
        __syncthreads();
        #pragma unroll
        for (int i = 0; i < 4; i++) {
            int idx = t + i * 256;
            int r = idx >> 3, c4 = (idx & 7) * 4;
            float4 v = *reinterpret_cast<const float4*>(&A[(size_t)(row0 + r) * lda + k0 + c4]);
            float f[4] = {v.x, v.y, v.z, v.w};
            #pragma unroll
            for (int j = 0; j < 4; j++) {
                uint32_t hi = f2tf(f[j]);
                Ah[r * 36 + c4 + j] = hi;
                if (SPLIT) Al[r * 36 + c4 + j] = f2tf(f[j] - __uint_as_float(hi));
            }
        }
        #pragma unroll
        for (int i = 0; i < 2; i++) {
            int idx = t + i * 256;
            int r = idx >> 3, c4 = (idx & 7) * 4;
            float4 v = *reinterpret_cast<const float4*>(&B[(size_t)(col0 + r) * ldb + k0 + c4]);
            float f[4] = {v.x, v.y, v.z, v.w};
            #pragma unroll
            for (int j = 0; j < 4; j++) {
                uint32_t hi = f2tf(f[j]);
                Bh[r * 36 + c4 + j] = hi;
                if (SPLIT) Bl[r * 36 + c4 + j] = f2tf(f[j] - __uint_as_float(hi));
            }
        }
        __syncthreads();

        #pragma unroll
        for (int ks = 0; ks < 4; ks++) {
            const int kb = ks * 8;
            uint32_t ah[4][4], al[4][4], bh[2][2], bl[2][2];
            #pragma unroll
            for (int mi = 0; mi < 4; mi++) {
                int rb = wm * 64 + mi * 16;
                ah[mi][0] = Ah[(rb + g    ) * 36 + kb + tg];
                ah[mi][1] = Ah[(rb + g + 8) * 36 + kb + tg];
                ah[mi][2] = Ah[(rb + g    ) * 36 + kb + tg + 4];
                ah[mi][3] = Ah[(rb + g + 8) * 36 + kb + tg + 4];
                if (SPLIT) {
                    al[mi][0] = Al[(rb + g    ) * 36 + kb + tg];
                    al[mi][1] = Al[(rb + g + 8) * 36 + kb + tg];
                    al[mi][2] = Al[(rb + g    ) * 36 + kb + tg + 4];
                    al[mi][3] = Al[(rb + g + 8) * 36 + kb + tg + 4];
                }
            }
            #pragma unroll
            for (int ni = 0; ni < 2; ni++) {
                int cb = wn * 16 + ni * 8;
                bh[ni][0] = Bh[(cb + g) * 36 + kb + tg];
                bh[ni][1] = Bh[(cb + g) * 36 + kb + tg + 4];
                if (SPLIT) {
                    bl[ni][0] = Bl[(cb + g) * 36 + kb + tg];
                    bl[ni][1] = Bl[(cb + g) * 36 + kb + tg + 4];
                }
            }
            #pragma unroll
            for (int mi = 0; mi < 4; mi++)
                #pragma unroll
                for (int ni = 0; ni < 2; ni++) {
                    float* c = acc[mi][ni];
                    mma8(c, ah[mi][0], ah[mi][1], ah[mi][2], ah[mi][3], bh[ni][0], bh[ni][1]);
                    if (SPLIT) {
                        mma8(c, ah[mi][0], ah[mi][1], ah[mi][2], ah[mi][3], bl[ni][0], bl[ni][1]);
                        mma8(c, al[mi][0], al[mi][1], al[mi][2], al[mi][3], bh[ni][0], bh[ni][1]);
                    }
                }
        }
    }

    #pragma unroll
    for (int mi = 0; mi < 4; mi++) {
        int r0 = row0 + wm * 64 + mi * 16 + g;
        #pragma unroll
        for (int ni = 0; ni < 2; ni++) {
            int c = col0 + wn * 16 + ni * 8 + 2 * tg;
            float b0 = bias[c], b1 = bias[c + 1];
            *reinterpret_cast<float2*>(&C[(size_t)r0       * ldc + c]) =
                make_float2(acc[mi][ni][0] + b0, acc[mi][ni][1] + b1);
            *reinterpret_cast<float2*>(&C[(size_t)(r0 + 8) * ldc + c]) =
                make_float2(acc[mi][ni][2] + b0, acc[mi][ni][3] + b1);
        }
    }
}

__global__ void __launch_bounds__(256) k_qkv(const float* __restrict__ x,
                                             const float* __restrict__ w,
                                             const float* __restrict__ b)
{
    gemm_v2<true>(x, EMB, w, EMB, g_qkv, FQKV, blockIdx.y * 128, blockIdx.x * 64, EMB, b);
}

__global__ void __launch_bounds__(256) k_out(const float* __restrict__ w,
                                             const float* __restrict__ b,
                                             float* __restrict__ out)
{
    gemm_v2<false>(g_oh, EMB, w, EMB, out, EMB, blockIdx.y * 128, blockIdx.x * 64, EMB, b);
}

// ===========================================================================
// Fused attention: per CTA = 32 query rows of one (b,h).
//   S = Q K^T * scale (3xTF32)  -> smem (32x1024 fp32)
//   softmax in smem; write attn probs to gmem once; re-store P as tf32 bits
//   O = P V (plain tf32)        -> g_oh
// smem: S 32*1032 + Qh/Ql 32*72 + Kh/Kl 64*72 = 187392 B
// ===========================================================================
#define SSTR 1032
#define TSTR 72

__global__ void __launch_bounds__(256) k_attn(float* __restrict__ attn)
{
    extern __shared__ float sm[];
    float*    S  = sm;                                  // 33024 floats
    uint32_t* Qh = (uint32_t*)(sm + 32 * SSTR);
    uint32_t* Ql = Qh + 32 * TSTR;
    uint32_t* Kh = Ql + 32 * TSTR;                      // V tile reuses this
    uint32_t* Kl = Kh + 64 * TSTR;

    const int bh = blockIdx.y;
    const int bb = bh / NHEAD, h = bh % NHEAD;
    const int row0 = blockIdx.x * 32;
    const int t = threadIdx.x, warp = t >> 5, lane = t & 31;
    const int g = lane >> 2, tg = lane & 3;
    const int wm = warp >> 2, wn = warp & 3;

    const float* Qg = g_qkv + ((size_t)bb * SEQ + row0) * FQKV + h * HDIM;
    const float* Kg = g_qkv + (size_t)bb * SEQ * FQKV + EMB     + h * HDIM;
    const float* Vg = g_qkv + (size_t)bb * SEQ * FQKV + 2 * EMB + h * HDIM;

    // ---- Phase 0: Q -> smem (hi/lo tf32) ----
    #pragma unroll
    for (int i = 0; i < 2; i++) {
        int idx = t + i * 256;
        int r = idx >> 4, c4 = (idx & 15) * 4;
        float4 v = *reinterpret_cast<const float4*>(&Qg[(size_t)r * FQKV + c4]);
        float f[4] = {v.x, v.y, v.z, v.w};
        #pragma unroll
        for (int j = 0; j < 4; j++) {
            uint32_t hi = f2tf(f[j]);
            Qh[r * TSTR + c4 + j] = hi;
            Ql[r * TSTR + c4 + j] = f2tf(f[j] - __uint_as_float(hi));
        }
    }

    // ---- Phase 1: S = Q K^T * 0.125 (3xTF32), 64-col strips ----
    for (int n0 = 0; n0 < SEQ; n0 += 64) {
        __syncthreads();
        #pragma unroll
        for (int i = 0; i < 4; i++) {
            int idx = t + i * 256;
            int r = idx >> 4, c4 = (idx & 15) * 4;
            float4 v = *reinterpret_cast<const float4*>(&Kg[(size_t)(n0 + r) * FQKV + c4]);
            float f[4] = {v.x, v.y, v.z, v.w};
            #pragma unroll
            for (int j = 0; j < 4; j++) {
                uint32_t hi = f2tf(f[j]);
                Kh[r * TSTR + c4 + j] = hi;
                Kl[r * TSTR + c4 + j] = f2tf(f[j] - __uint_as_float(hi));
            }
        }
        __syncthreads();

        float acc[2][4] = {};
        #pragma unroll
        for (int ks = 0; ks < 8; ks++) {
            const int kb = ks * 8;
            const int ra = wm * 16;
            uint32_t ah[4], al[4];
            ah[0] = Qh[(ra + g    ) * TSTR + kb + tg];
            ah[1] = Qh[(ra + g + 8) * TSTR + kb + tg];
            ah[2] = Qh[(ra + g    ) * TSTR + kb + tg + 4];
            ah[3] = Qh[(ra + g + 8) * TSTR + kb + tg + 4];
            al[0] = Ql[(ra + g    ) * TSTR + kb + tg];
            al[1] = Ql[(ra + g + 8) * TSTR + kb + tg];
            al[2] = Ql[(ra + g    ) * TSTR + kb + tg + 4];
            al[3] = Ql[(ra + g + 8) * TSTR + kb + tg + 4];
            #pragma unroll
            for (int ni = 0; ni < 2; ni++) {
                int cb = wn * 16 + ni * 8;
                uint32_t b0 = Kh[(cb + g) * TSTR + kb + tg];
                uint32_t b1 = Kh[(cb + g) * TSTR + kb + tg + 4];
                uint32_t l0 = Kl[(cb + g) * TSTR + kb + tg];
                uint32_t l1 = Kl[(cb + g) * TSTR + kb + tg + 4];
                mma8(acc[ni], ah[0], ah[1], ah[2], ah[3], b0, b1);
                mma8(acc[ni], ah[0], ah[1], ah[2], ah[3], l0, l1);
                mma8(acc[ni], al[0], al[1], al[2], al[3], b0, b1);
            }
        }
        #pragma unroll
        for (int ni = 0; ni < 2; ni++) {
            int r = wm * 16 + g;
            int c = n0 + wn * 16 + ni * 8 + 2 * tg;
            S[(size_t)r       * SSTR + c]     = acc[ni][0] * 0.125f;
            S[(size_t)r       * SSTR + c + 1] = acc[ni][1] * 0.125f;
            S[(size_t)(r + 8) * SSTR + c]     = acc[ni][2] * 0.125f;
            S[(size_t)(r + 8) * SSTR + c + 1] = acc[ni][3] * 0.125f;
        }
    }
    __syncthreads();

    // ---- Phase 2: softmax rows; write attn to gmem; store P as tf32 bits ----
    #pragma unroll
    for (int j = 0; j < 4; j++) {
        int r = warp + j * 8;
        float* Sr = S + (size_t)r * SSTR;

        float m = -1e30f;
        #pragma unroll
        for (int it = 0; it < 8; it++) {
            float4 v = *reinterpret_cast<float4*>(&Sr[(it * 32 + lane) * 4]);
            m = fmaxf(m, fmaxf(fmaxf(v.x, v.y), fmaxf(v.z, v.w)));
        }
        #pragma unroll
        for (int o = 16; o > 0; o >>= 1) m = fmaxf(m, __shfl_xor_sync(0xffffffffu, m, o));

        float s = 0.0f;
        #pragma unroll
        for (int it = 0; it < 8; it++) {
            float4 v = *reinterpret_cast<float4*>(&Sr[(it * 32 + lane) * 4]);
            v.x = __expf(v.x - m); v.y = __expf(v.y - m);
            v.z = __expf(v.z - m); v.w = __expf(v.w - m);
            s += v.x + v.y + v.z + v.w;
            *reinterpret_cast<float4*>(&Sr[(it * 32 + lane) * 4]) = v;
        }
        #pragma unroll
        for (int o = 16; o > 0; o >>= 1) s += __shfl_xor_sync(0xffffffffu, s, o);
        float inv = 1.0f / s;

        float* arow = attn + ((size_t)bh * SEQ + row0 + r) * SEQ;
        #pragma unroll
        for (int it = 0; it < 8; it++) {
            float4 v = *reinterpret_cast<float4*>(&Sr[(it * 32 + lane) * 4]);
            v.x *= inv; v.y *= inv; v.z *= inv; v.w *= inv;
            *reinterpret_cast<float4*>(&arow[(it * 32 + lane) * 4]) = v;
            uint4 u = make_uint4(f2tf(v.x), f2tf(v.y), f2tf(v.z), f2tf(v.w));
            *reinterpret_cast<uint4*>(&Sr[(it * 32 + lane) * 4]) = u;
        }
    }

    // ---- Phase 3: O = P V (plain tf32) ----
    const uint32_t* Pt = (const uint32_t*)S;
    uint32_t* Vh = Kh;
    float acc2[2][4] = {};
    for (int k0 = 0; k0 < SEQ; k0 += 64) {
        __syncthreads();
        #pragma unroll
        for (int i = 0; i < 4; i++) {
            int idx = t + i * 256;
            int r = idx >> 4, c4 = (idx & 15) * 4;
            float4 v = *reinterpret_cast<const float4*>(&Vg[(size_t)(k0 + r) * FQKV + c4]);
            // transpose: Vh[n][k] with stride 65 (store-conflict friendly)
            Vh[(c4 + 0) * 65 + r] = f2tf(v.x);
            Vh[(c4 + 1) * 65 + r] = f2tf(v.y);
            Vh[(c4 + 2) * 65 + r] = f2tf(v.z);
            Vh[(c4 + 3) * 65 + r] = f2tf(v.w);
        }
        __syncthreads();
        #pragma unroll
        for (int ks = 0; ks < 8; ks++) {
            const int kb = ks * 8;
            uint32_t b0 = Vh[(warp * 8 + g) * 65 + kb + tg];
            uint32_t b1 = Vh[(warp * 8 + g) * 65 + kb + tg + 4];
            #pragma unroll
            for (int mi = 0; mi < 2; mi++) {
                uint32_t a0 = Pt[(size_t)(mi * 16 + g    ) * SSTR + k0 + kb + tg];
                uint32_t a1 = Pt[(size_t)(mi * 16 + g + 8) * SSTR + k0 + kb + tg];
                uint32_t a2 = Pt[(size_t)(mi * 16 + g    ) * SSTR + k0 + kb + tg + 4];
                uint32_t a3 = Pt[(size_t)(mi * 16 + g + 8) * SSTR + k0 + kb + tg + 4];
                mma8(acc2[mi], a0, a1, a2, a3, b0, b1);
            }
        }
    }
    #pragma unroll
    for (int mi = 0; mi < 2; mi++) {
        int r = row0 + mi * 16 + g;
        int c = h * HDIM + warp * 8 + 2 * tg;
        *reinterpret_cast<float2*>(&g_oh[((size_t)bb * SEQ + r    ) * EMB + c]) =
            make_float2(acc2[mi][0], acc2[mi][1]);
        *reinterpret_cast<float2*>(&g_oh[((size_t)bb * SEQ + r + 8) * EMB + c]) =
            make_float2(acc2[mi][2], acc2[mi][3]);
    }
}

// ---------------------------------------------------------------------------
extern "C" void kernel_launch(void* const* d_in, const int* in_sizes, int n_in,
                              void* d_out, int out_size)
{
    const float* x     = (const float*)d_in[0];
    const float* w_qkv = (const float*)d_in[1];
    const float* b_qkv = (const float*)d_in[2];
    const float* w_out = (const float*)d_in[3];
    const float* b_out = (const float*)d_in[4];

    float* out  = (float*)d_out;
    float* attn = out + (size_t)MTOT * EMB;

    const int smem_qkv  = (2 * 128 * 36 + 2 * 64 * 36) * 4;        // 55296
    const int smem_out  = (128 * 36 + 64 * 36) * 4;                // 27648
    const int smem_attn = (32 * SSTR + 2 * 32 * TSTR + 2 * 64 * TSTR) * 4; // 187392

    static bool attr_done = false;
    if (!attr_done) {
        cudaFuncSetAttribute(k_qkv,  cudaFuncAttributeMaxDynamicSharedMemorySize, smem_qkv);
        cudaFuncSetAttribute(k_out,  cudaFuncAttributeMaxDynamicSharedMemorySize, smem_out);
        cudaFuncSetAttribute(k_attn, cudaFuncAttributeMaxDynamicSharedMemorySize, smem_attn);
        attr_done = true;
    }

    k_qkv <<<dim3(FQKV / 64, MTOT / 128), 256, smem_qkv >>>(x, w_qkv, b_qkv);
    k_attn<<<dim3(SEQ / 32, BHTOT),       256, smem_attn>>>(attn);
    k_out <<<dim3(EMB / 64, MTOT / 128),  256, smem_out >>>(w_out, b_out, out);
}

// round 4
// speedup vs baseline: 1.3943x; 1.3943x over previous
#include <cuda_runtime.h>
#include <math.h>
#include <stdint.h>

#define EMB   768
#define NHEAD 12
#define HDIM  64
#define SEQ   1024
#define BATCH 8
#define MTOT  (BATCH * SEQ)
#define FQKV  (3 * EMB)
#define BHTOT (BATCH * NHEAD)

__device__ float g_qkv[(size_t)MTOT * FQKV];   // 75.5 MB
__device__ float g_oh [(size_t)MTOT * EMB];    // 25.2 MB

__device__ __forceinline__ uint32_t f2tf(float x) {
    uint32_t r;
    asm("cvt.rna.tf32.f32 %0, %1;" : "=r"(r) : "f"(x));
    return r;
}

__device__ __forceinline__ void mma8(float* c,
                                     uint32_t a0, uint32_t a1, uint32_t a2, uint32_t a3,
                                     uint32_t b0, uint32_t b1)
{
    asm volatile(
        "mma.sync.aligned.m16n8k8.row.col.f32.tf32.tf32.f32 "
        "{%0,%1,%2,%3}, {%4,%5,%6,%7}, {%8,%9}, {%0,%1,%2,%3};\n"
        : "+f"(c[0]), "+f"(c[1]), "+f"(c[2]), "+f"(c[3])
        : "r"(a0), "r"(a1), "r"(a2), "r"(a3), "r"(b0), "r"(b1));
}

// ===========================================================================
// Weight GEMM: C = A * B^T + bias.  Block 128x64, 256 thr.
// tf32 converted at smem-store time; register prefetch of next k-chunk.
// ===========================================================================
template<bool SPLIT>
__device__ __forceinline__ void gemm_v3(
    const float* __restrict__ A, int lda,
    const float* __restrict__ B, int ldb,
    float*       __restrict__ C, int ldc,
    int row0, int col0, int K,
    const float* __restrict__ bias)
{
    extern __shared__ uint32_t smu[];
    uint32_t* Ah = smu;
    uint32_t* Al = SPLIT ? Ah + 128 * 36 : (uint32_t*)0;
    uint32_t* Bh = Ah + (SPLIT ? 2 : 1) * 128 * 36;
    uint32_t* Bl = SPLIT ? Bh + 64 * 36 : (uint32_t*)0;

    const int t = threadIdx.x, warp = t >> 5, lane = t & 31;
    const int wm = warp >> 2, wn = warp & 3;
    const int g = lane >> 2, tg = lane & 3;

    float acc[4][2][4] = {};
    float4 pa[4], pb[2];

    // prologue: load chunk 0
    #pragma unroll
    for (int i = 0; i < 4; i++) {
        int idx = t + i * 256;
        int r = idx >> 3, c4 = (idx & 7) * 4;
        pa[i] = *reinterpret_cast<const float4*>(&A[(size_t)(row0 + r) * lda + c4]);
    }
    #pragma unroll
    for (int i = 0; i < 2; i++) {
        int idx = t + i * 256;
        int r = idx >> 3, c4 = (idx & 7) * 4;
        pb[i] = *reinterpret_cast<const float4*>(&B[(size_t)(col0 + r) * ldb + c4]);
    }

    for (int k0 = 0; k0 < K; k0 += 32) {
        __syncthreads();   // previous MMA phase done with smem
        // store (+convert) staged regs
        #pragma unroll
        for (int i = 0; i < 4; i++) {
            int idx = t + i * 256;
            int r = idx >> 3, c4 = (idx & 7) * 4;
            float f[4] = {pa[i].x, pa[i].y, pa[i].z, pa[i].w};
            #pragma unroll
            for (int j = 0; j < 4; j++) {
                uint32_t hi = f2tf(f[j]);
                Ah[r * 36 + c4 + j] = hi;
                if (SPLIT) Al[r * 36 + c4 + j] = f2tf(f[j] - __uint_as_float(hi));
            }
        }
        #pragma unroll
        for (int i = 0; i < 2; i++) {
            int idx = t + i * 256;
            int r = idx >> 3, c4 = (idx & 7) * 4;
            float f[4] = {pb[i].x, pb[i].y, pb[i].z, pb[i].w};
            #pragma unroll
            for (int j = 0; j < 4; j++) {
                uint32_t hi = f2tf(f[j]);
                Bh[r * 36 + c4 + j] = hi;
                if (SPLIT) Bl[r * 36 + c4 + j] = f2tf(f[j] - __uint_as_float(hi));
            }
        }
        __syncthreads();

        // prefetch next chunk (overlaps MMA below)
        int kn = k0 + 32;
        if (kn < K) {
            #pragma unroll
            for (int i = 0; i < 4; i++) {
                int idx = t + i * 256;
                int r = idx >> 3, c4 = (idx & 7) * 4;
                pa[i] = *reinterpret_cast<const float4*>(&A[(size_t)(row0 + r) * lda + kn + c4]);
            }
            #pragma unroll
            for (int i = 0; i < 2; i++) {
                int idx = t + i * 256;
                int r = idx >> 3, c4 = (idx & 7) * 4;
                pb[i] = *reinterpret_cast<const float4*>(&B[(size_t)(col0 + r) * ldb + kn + c4]);
            }
        }

        #pragma unroll
        for (int ks = 0; ks < 4; ks++) {
            const int kb = ks * 8;
            uint32_t ah[4][4], al[4][4], bh[2][2], bl[2][2];
            #pragma unroll
            for (int mi = 0; mi < 4; mi++) {
                int rb = wm * 64 + mi * 16;
                ah[mi][0] = Ah[(rb + g    ) * 36 + kb + tg];
                ah[mi][1] = Ah[(rb + g + 8) * 36 + kb + tg];
                ah[mi][2] = Ah[(rb + g    ) * 36 + kb + tg + 4];
                ah[mi][3] = Ah[(rb + g + 8) * 36 + kb + tg + 4];
                if (SPLIT) {
                    al[mi][0] = Al[(rb + g    ) * 36 + kb + tg];
                    al[mi][1] = Al[(rb + g + 8) * 36 + kb + tg];
                    al[mi][2] = Al[(rb + g    ) * 36 + kb + tg + 4];
                    al[mi][3] = Al[(rb + g + 8) * 36 + kb + tg + 4];
                }
            }
            #pragma unroll
            for (int ni = 0; ni < 2; ni++) {
                int cb = wn * 16 + ni * 8;
                bh[ni][0] = Bh[(cb + g) * 36 + kb + tg];
                bh[ni][1] = Bh[(cb + g) * 36 + kb + tg + 4];
                if (SPLIT) {
                    bl[ni][0] = Bl[(cb + g) * 36 + kb + tg];
                    bl[ni][1] = Bl[(cb + g) * 36 + kb + tg + 4];
                }
            }
            #pragma unroll
            for (int mi = 0; mi < 4; mi++)
                #pragma unroll
                for (int ni = 0; ni < 2; ni++) {
                    float* c = acc[mi][ni];
                    mma8(c, ah[mi][0], ah[mi][1], ah[mi][2], ah[mi][3], bh[ni][0], bh[ni][1]);
                    if (SPLIT) {
                        mma8(c, ah[mi][0], ah[mi][1], ah[mi][2], ah[mi][3], bl[ni][0], bl[ni][1]);
                        mma8(c, al[mi][0], al[mi][1], al[mi][2], al[mi][3], bh[ni][0], bh[ni][1]);
                    }
                }
        }
    }

    #pragma unroll
    for (int mi = 0; mi < 4; mi++) {
        int r0 = row0 + wm * 64 + mi * 16 + g;
        #pragma unroll
        for (int ni = 0; ni < 2; ni++) {
            int c = col0 + wn * 16 + ni * 8 + 2 * tg;
            float b0 = bias[c], b1 = bias[c + 1];
            *reinterpret_cast<float2*>(&C[(size_t)r0       * ldc + c]) =
                make_float2(acc[mi][ni][0] + b0, acc[mi][ni][1] + b1);
            *reinterpret_cast<float2*>(&C[(size_t)(r0 + 8) * ldc + c]) =
                make_float2(acc[mi][ni][2] + b0, acc[mi][ni][3] + b1);
        }
    }
}

__global__ void __launch_bounds__(256) k_qkv(const float* __restrict__ x,
                                             const float* __restrict__ w,
                                             const float* __restrict__ b)
{
    gemm_v3<true>(x, EMB, w, EMB, g_qkv, FQKV, blockIdx.y * 128, blockIdx.x * 64, EMB, b);
}

__global__ void __launch_bounds__(256) k_out(const float* __restrict__ w,
                                             const float* __restrict__ b,
                                             float* __restrict__ out)
{
    gemm_v3<false>(g_oh, EMB, w, EMB, out, EMB, blockIdx.y * 128, blockIdx.x * 64, EMB, b);
}

// ===========================================================================
// Scores: S = Q K^T * 0.125, plain tf32.  CTA = 128 rows x 64 cols, K=64.
// Q/K tiles converted once at load. 8 warps as 4m x 2n, warp tile 32x32.
// ===========================================================================
#define QSTR 68

__global__ void __launch_bounds__(256) k_scores(float* __restrict__ attn)
{
    extern __shared__ uint32_t smq[];
    uint32_t* Qh = smq;              // 128*68
    uint32_t* Kh = Qh + 128 * QSTR;  // 64*68

    const int bh = blockIdx.z;
    const int bb = bh / NHEAD, h = bh % NHEAD;
    const int row0 = blockIdx.y * 128, col0 = blockIdx.x * 64;
    const int t = threadIdx.x, warp = t >> 5, lane = t & 31;
    const int wm = warp >> 1, wn = warp & 1;
    const int g = lane >> 2, tg = lane & 3;

    const float* Qg = g_qkv + ((size_t)bb * SEQ + row0) * FQKV + h * HDIM;
    const float* Kg = g_qkv + ((size_t)bb * SEQ + col0) * FQKV + EMB + h * HDIM;

    #pragma unroll
    for (int i = 0; i < 8; i++) {
        int idx = t + i * 256;
        int r = idx >> 4, c4 = (idx & 15) * 4;
        float4 v = *reinterpret_cast<const float4*>(&Qg[(size_t)r * FQKV + c4]);
        Qh[r * QSTR + c4 + 0] = f2tf(v.x); Qh[r * QSTR + c4 + 1] = f2tf(v.y);
        Qh[r * QSTR + c4 + 2] = f2tf(v.z); Qh[r * QSTR + c4 + 3] = f2tf(v.w);
    }
    #pragma unroll
    for (int i = 0; i < 4; i++) {
        int idx = t + i * 256;
        int r = idx >> 4, c4 = (idx & 15) * 4;
        float4 v = *reinterpret_cast<const float4*>(&Kg[(size_t)r * FQKV + c4]);
        Kh[r * QSTR + c4 + 0] = f2tf(v.x); Kh[r * QSTR + c4 + 1] = f2tf(v.y);
        Kh[r * QSTR + c4 + 2] = f2tf(v.z); Kh[r * QSTR + c4 + 3] = f2tf(v.w);
    }
    __syncthreads();

    float acc[2][4][4] = {};
    #pragma unroll
    for (int ks = 0; ks < 8; ks++) {
        const int kb = ks * 8;
        uint32_t a[2][4], bfr[4][2];
        #pragma unroll
        for (int mi = 0; mi < 2; mi++) {
            int rb = wm * 32 + mi * 16;
            a[mi][0] = Qh[(rb + g    ) * QSTR + kb + tg];
            a[mi][1] = Qh[(rb + g + 8) * QSTR + kb + tg];
            a[mi][2] = Qh[(rb + g    ) * QSTR + kb + tg + 4];
            a[mi][3] = Qh[(rb + g + 8) * QSTR + kb + tg + 4];
        }
        #pragma unroll
        for (int ni = 0; ni < 4; ni++) {
            int cb = wn * 32 + ni * 8;
            bfr[ni][0] = Kh[(cb + g) * QSTR + kb + tg];
            bfr[ni][1] = Kh[(cb + g) * QSTR + kb + tg + 4];
        }
        #pragma unroll
        for (int mi = 0; mi < 2; mi++)
            #pragma unroll
            for (int ni = 0; ni < 4; ni++)
                mma8(acc[mi][ni], a[mi][0], a[mi][1], a[mi][2], a[mi][3],
                     bfr[ni][0], bfr[ni][1]);
    }

    float* S = attn + (size_t)bh * SEQ * SEQ;
    #pragma unroll
    for (int mi = 0; mi < 2; mi++) {
        int r = row0 + wm * 32 + mi * 16 + g;
        #pragma unroll
        for (int ni = 0; ni < 4; ni++) {
            int c = col0 + wn * 32 + ni * 8 + 2 * tg;
            *reinterpret_cast<float2*>(&S[(size_t)r       * SEQ + c]) =
                make_float2(acc[mi][ni][0] * 0.125f, acc[mi][ni][1] * 0.125f);
            *reinterpret_cast<float2*>(&S[(size_t)(r + 8) * SEQ + c]) =
                make_float2(acc[mi][ni][2] * 0.125f, acc[mi][ni][3] * 0.125f);
        }
    }
}

// ===========================================================================
// Fused softmax + PV. CTA = 32 rows of one (b,h).
// Read raw S from gmem once -> smem; softmax; write probs to gmem once;
// P (tf32 bits, in smem) @ V (double-buffered smem, register-staged).
// ===========================================================================
#define SSTR 1032
#define VSTR 65

__device__ __forceinline__ void load_v_regs(const float* __restrict__ Vg,
                                            int k0, int t, float4* r4)
{
    #pragma unroll
    for (int i = 0; i < 4; i++) {
        int idx = t + i * 256;
        int r = idx >> 4, c4 = (idx & 15) * 4;
        r4[i] = *reinterpret_cast<const float4*>(&Vg[(size_t)(k0 + r) * FQKV + c4]);
    }
}

__device__ __forceinline__ void store_v_smem(uint32_t* __restrict__ Vb,
                                             int t, const float4* r4)
{
    #pragma unroll
    for (int i = 0; i < 4; i++) {
        int idx = t + i * 256;
        int r = idx >> 4, c4 = (idx & 15) * 4;
        Vb[(c4 + 0) * VSTR + r] = f2tf(r4[i].x);
        Vb[(c4 + 1) * VSTR + r] = f2tf(r4[i].y);
        Vb[(c4 + 2) * VSTR + r] = f2tf(r4[i].z);
        Vb[(c4 + 3) * VSTR + r] = f2tf(r4[i].w);
    }
}

__global__ void __launch_bounds__(256) k_spv(float* __restrict__ attn)
{
    extern __shared__ float sm[];
    float*    S  = sm;                                   // 32*1032
    uint32_t* V0 = (uint32_t*)(sm + 32 * SSTR);
    uint32_t* V1 = V0 + 64 * VSTR;

    const int bh = blockIdx.y;
    const int bb = bh / NHEAD, h = bh % NHEAD;
    const int row0 = blockIdx.x * 32;
    const int t = threadIdx.x, warp = t >> 5, lane = t & 31;
    const int g = lane >> 2, tg = lane & 3;

    const float* Vg = g_qkv + (size_t)bb * SEQ * FQKV + 2 * EMB + h * HDIM;
    float* Sg = attn + ((size_t)bh * SEQ + row0) * SEQ;

    // ---- load raw S block (32 x 1024) ----
    #pragma unroll
    for (int i = 0; i < 32; i++) {
        int idx = t + i * 256;
        int row = idx >> 8, c = (idx & 255) * 4;
        float4 v = *reinterpret_cast<const float4*>(&Sg[(size_t)row * SEQ + c]);
        *reinterpret_cast<float4*>(&S[(size_t)row * SSTR + c]) = v;
    }
    __syncthreads();

    // ---- softmax per row (4 rows/warp); write probs; restore tf32 bits ----
    #pragma unroll
    for (int j = 0; j < 4; j++) {
        int r = warp + j * 8;
        float* Sr = S + (size_t)r * SSTR;

        float m = -1e30f;
        #pragma unroll
        for (int it = 0; it < 8; it++) {
            float4 v = *reinterpret_cast<float4*>(&Sr[(it * 32 + lane) * 4]);
            m = fmaxf(m, fmaxf(fmaxf(v.x, v.y), fmaxf(v.z, v.w)));
        }
        #pragma unroll
        for (int o = 16; o > 0; o >>= 1) m = fmaxf(m, __shfl_xor_sync(0xffffffffu, m, o));

        float s = 0.0f;
        #pragma unroll
        for (int it = 0; it < 8; it++) {
            float4 v = *reinterpret_cast<float4*>(&Sr[(it * 32 + lane) * 4]);
            v.x = __expf(v.x - m); v.y = __expf(v.y - m);
            v.z = __expf(v.z - m); v.w = __expf(v.w - m);
            s += v.x + v.y + v.z + v.w;
            *reinterpret_cast<float4*>(&Sr[(it * 32 + lane) * 4]) = v;
        }
        #pragma unroll
        for (int o = 16; o > 0; o >>= 1) s += __shfl_xor_sync(0xffffffffu, s, o);
        float inv = 1.0f / s;

        float* arow = Sg + (size_t)r * SEQ;
        #pragma unroll
        for (int it = 0; it < 8; it++) {
            float4 v = *reinterpret_cast<float4*>(&Sr[(it * 32 + lane) * 4]);
            v.x *= inv; v.y *= inv; v.z *= inv; v.w *= inv;
            *reinterpret_cast<float4*>(&arow[(it * 32 + lane) * 4]) = v;
            uint4 u = make_uint4(f2tf(v.x), f2tf(v.y), f2tf(v.z), f2tf(v.w));
            *reinterpret_cast<uint4*>(&Sr[(it * 32 + lane) * 4]) = u;
        }
    }

    // ---- PV: O(32x64) = P(32x1024) @ V(1024x64), double-buffered V ----
    const uint32_t* Pt = (const uint32_t*)S;
    float4 vr[4];
    float acc2[2][4] = {};

    load_v_regs(Vg, 0, t, vr);
    __syncthreads();               // P bits visible to all warps
    store_v_smem(V0, t, vr);

    for (int st = 0; st < 16; st++) {
        if (st < 15) load_v_regs(Vg, (st + 1) * 64, t, vr);
        __syncthreads();           // current V buffer visible
        uint32_t* Vb = (st & 1) ? V1 : V0;
        const int k0 = st * 64;
        #pragma unroll
        for (int ks = 0; ks < 8; ks++) {
            const int kb = ks * 8;
            uint32_t b0 = Vb[(warp * 8 + g) * VSTR + kb + tg];
            uint32_t b1 = Vb[(warp * 8 + g) * VSTR + kb + tg + 4];
            #pragma unroll
            for (int mi = 0; mi < 2; mi++) {
                uint32_t a0 = Pt[(size_t)(mi * 16 + g    ) * SSTR + k0 + kb + tg];
                uint32_t a1 = Pt[(size_t)(mi * 16 + g + 8) * SSTR + k0 + kb + tg];
                uint32_t a2 = Pt[(size_t)(mi * 16 + g    ) * SSTR + k0 + kb + tg + 4];
                uint32_t a3 = Pt[(size_t)(mi * 16 + g + 8) * SSTR + k0 + kb + tg + 4];
                mma8(acc2[mi], a0, a1, a2, a3, b0, b1);
            }
        }
        if (st < 15) store_v_smem((st & 1) ? V0 : V1, t, vr);
    }

    #pragma unroll
    for (int mi = 0; mi < 2; mi++) {
        int r = row0 + mi * 16 + g;
        int c = h * HDIM + warp * 8 + 2 * tg;
        *reinterpret_cast<float2*>(&g_oh[((size_t)bb * SEQ + r    ) * EMB + c]) =
            make_float2(acc2[mi][0], acc2[mi][1]);
        *reinterpret_cast<float2*>(&g_oh[((size_t)bb * SEQ + r + 8) * EMB + c]) =
            make_float2(acc2[mi][2], acc2[mi][3]);
    }
}

// ---------------------------------------------------------------------------
extern "C" void kernel_launch(void* const* d_in, const int* in_sizes, int n_in,
                              void* d_out, int out_size)
{
    const float* x     = (const float*)d_in[0];
    const float* w_qkv = (const float*)d_in[1];
    const float* b_qkv = (const float*)d_in[2];
    const float* w_out = (const float*)d_in[3];
    const float* b_out = (const float*)d_in[4];

    float* out  = (float*)d_out;
    float* attn = out + (size_t)MTOT * EMB;

    const int smem_qkv    = (2 * 128 * 36 + 2 * 64 * 36) * 4;      // 55296
    const int smem_out    = (128 * 36 + 64 * 36) * 4;              // 27648
    const int smem_scores = (128 * QSTR + 64 * QSTR) * 4;          // 52224
    const int smem_spv    = (32 * SSTR + 2 * 64 * VSTR) * 4;       // 165376

    static bool attr_done = false;
    if (!attr_done) {
        cudaFuncSetAttribute(k_qkv,    cudaFuncAttributeMaxDynamicSharedMemorySize, smem_qkv);
        cudaFuncSetAttribute(k_out,    cudaFuncAttributeMaxDynamicSharedMemorySize, smem_out);
        cudaFuncSetAttribute(k_scores, cudaFuncAttributeMaxDynamicSharedMemorySize, smem_scores);
        cudaFuncSetAttribute(k_spv,    cudaFuncAttributeMaxDynamicSharedMemorySize, smem_spv);
        attr_done = true;
    }

    k_qkv   <<<dim3(FQKV / 64, MTOT / 128), 256, smem_qkv   >>>(x, w_qkv, b_qkv);
    k_scores<<<dim3(SEQ / 64, SEQ / 128, BHTOT), 256, smem_scores>>>(attn);
    k_spv   <<<dim3(SEQ / 32, BHTOT), 256, smem_spv  >>>(attn);
    k_out   <<<dim3(EMB / 64, MTOT / 128), 256, smem_out   >>>(w_out, b_out, out);
}

// round 5
// speedup vs baseline: 1.6366x; 1.1738x over previous
#include <cuda_runtime.h>
#include <cuda_bf16.h>
#include <math.h>
#include <stdint.h>

#define EMB   768
#define NHEAD 12
#define HDIM  64
#define SEQ   1024
#define BATCH 8
#define MTOT  (BATCH * SEQ)
#define FQKV  (3 * EMB)
#define BHTOT (BATCH * NHEAD)

__device__ float g_qkv[(size_t)MTOT * FQKV];   // 75.5 MB
__device__ float g_oh [(size_t)MTOT * EMB];    // 25.2 MB

__device__ __forceinline__ uint32_t f2tf(float x) {
    uint32_t r;
    asm("cvt.rna.tf32.f32 %0, %1;" : "=r"(r) : "f"(x));
    return r;
}

__device__ __forceinline__ void mma8(float* c,
                                     uint32_t a0, uint32_t a1, uint32_t a2, uint32_t a3,
                                     uint32_t b0, uint32_t b1)
{
    asm volatile(
        "mma.sync.aligned.m16n8k8.row.col.f32.tf32.tf32.f32 "
        "{%0,%1,%2,%3}, {%4,%5,%6,%7}, {%8,%9}, {%0,%1,%2,%3};\n"
        : "+f"(c[0]), "+f"(c[1]), "+f"(c[2]), "+f"(c[3])
        : "r"(a0), "r"(a1), "r"(a2), "r"(a3), "r"(b0), "r"(b1));
}

__device__ __forceinline__ void mma16(float* c, const uint32_t* a,
                                      uint32_t b0, uint32_t b1)
{
    asm volatile(
        "mma.sync.aligned.m16n8k16.row.col.f32.bf16.bf16.f32 "
        "{%0,%1,%2,%3}, {%4,%5,%6,%7}, {%8,%9}, {%0,%1,%2,%3};\n"
        : "+f"(c[0]), "+f"(c[1]), "+f"(c[2]), "+f"(c[3])
        : "r"(a[0]), "r"(a[1]), "r"(a[2]), "r"(a[3]), "r"(b0), "r"(b1));
}

// split pair (x,y) into packed bf16x2 hi + residual lo (x -> low 16 bits = even k)
__device__ __forceinline__ void bf16_split2(float x, float y,
                                            uint32_t& hi, uint32_t& lo)
{
    __nv_bfloat162 h = __floats2bfloat162_rn(x, y);
    hi = *reinterpret_cast<uint32_t*>(&h);
    float rx = x - __bfloat162float(h.x);
    float ry = y - __bfloat162float(h.y);
    __nv_bfloat162 l = __floats2bfloat162_rn(rx, ry);
    lo = *reinterpret_cast<uint32_t*>(&l);
}

// ===========================================================================
// QKV projection: C = A*B^T + bias, split-bf16 (3x m16n8k16 per k16).
// Block 128x64, 256 thr, register prefetch of next k-chunk (32).
// ===========================================================================
#define PSTR 20   // 16 bf16x2 pairs per 32-k chunk + 4 pad

__global__ void __launch_bounds__(256) k_qkv(const float* __restrict__ x,
                                             const float* __restrict__ w,
                                             const float* __restrict__ bias)
{
    extern __shared__ uint32_t smu[];
    uint32_t* Ah = smu;                // 128*PSTR
    uint32_t* Al = Ah + 128 * PSTR;
    uint32_t* Bh = Al + 128 * PSTR;    // 64*PSTR
    uint32_t* Bl = Bh + 64 * PSTR;

    const int row0 = blockIdx.y * 128, col0 = blockIdx.x * 64;
    const int t = threadIdx.x, warp = t >> 5, lane = t & 31;
    const int wm = warp >> 2, wn = warp & 3;
    const int g = lane >> 2, tg = lane & 3;

    const float* A = x;
    const float* B = w;

    float acc[4][2][4] = {};
    float4 pa[4], pb[2];

    #pragma unroll
    for (int i = 0; i < 4; i++) {
        int idx = t + i * 256;
        int r = idx >> 3, c4 = (idx & 7) * 4;
        pa[i] = *reinterpret_cast<const float4*>(&A[(size_t)(row0 + r) * EMB + c4]);
    }
    #pragma unroll
    for (int i = 0; i < 2; i++) {
        int idx = t + i * 256;
        int r = idx >> 3, c4 = (idx & 7) * 4;
        pb[i] = *reinterpret_cast<const float4*>(&B[(size_t)(col0 + r) * EMB + c4]);
    }

    for (int k0 = 0; k0 < EMB; k0 += 32) {
        __syncthreads();
        #pragma unroll
        for (int i = 0; i < 4; i++) {
            int idx = t + i * 256;
            int r = idx >> 3, p0 = (idx & 7) * 2;
            uint32_t h0, l0, h1, l1;
            bf16_split2(pa[i].x, pa[i].y, h0, l0);
            bf16_split2(pa[i].z, pa[i].w, h1, l1);
            Ah[r * PSTR + p0] = h0; Ah[r * PSTR + p0 + 1] = h1;
            Al[r * PSTR + p0] = l0; Al[r * PSTR + p0 + 1] = l1;
        }
        #pragma unroll
        for (int i = 0; i < 2; i++) {
            int idx = t + i * 256;
            int r = idx >> 3, p0 = (idx & 7) * 2;
            uint32_t h0, l0, h1, l1;
            bf16_split2(pb[i].x, pb[i].y, h0, l0);
            bf16_split2(pb[i].z, pb[i].w, h1, l1);
            Bh[r * PSTR + p0] = h0; Bh[r * PSTR + p0 + 1] = h1;
            Bl[r * PSTR + p0] = l0; Bl[r * PSTR + p0 + 1] = l1;
        }
        __syncthreads();

        int kn = k0 + 32;
        if (kn < EMB) {
            #pragma unroll
            for (int i = 0; i < 4; i++) {
                int idx = t + i * 256;
                int r = idx >> 3, c4 = (idx & 7) * 4;
                pa[i] = *reinterpret_cast<const float4*>(&A[(size_t)(row0 + r) * EMB + kn + c4]);
            }
            #pragma unroll
            for (int i = 0; i < 2; i++) {
                int idx = t + i * 256;
                int r = idx >> 3, c4 = (idx & 7) * 4;
                pb[i] = *reinterpret_cast<const float4*>(&B[(size_t)(col0 + r) * EMB + kn + c4]);
            }
        }

        #pragma unroll
        for (int ks = 0; ks < 2; ks++) {
            const int pbase = ks * 8;
            uint32_t ah[4][4], al[4][4], bh[2][2], bl[2][2];
            #pragma unroll
            for (int mi = 0; mi < 4; mi++) {
                int rb = wm * 64 + mi * 16;
                ah[mi][0] = Ah[(rb + g    ) * PSTR + pbase + tg];
                ah[mi][1] = Ah[(rb + g + 8) * PSTR + pbase + tg];
                ah[mi][2] = Ah[(rb + g    ) * PSTR + pbase + tg + 4];
                ah[mi][3] = Ah[(rb + g + 8) * PSTR + pbase + tg + 4];
                al[mi][0] = Al[(rb + g    ) * PSTR + pbase + tg];
                al[mi][1] = Al[(rb + g + 8) * PSTR + pbase + tg];
                al[mi][2] = Al[(rb + g    ) * PSTR + pbase + tg + 4];
                al[mi][3] = Al[(rb + g + 8) * PSTR + pbase + tg + 4];
            }
            #pragma unroll
            for (int ni = 0; ni < 2; ni++) {
                int cb = wn * 16 + ni * 8;
                bh[ni][0] = Bh[(cb + g) * PSTR + pbase + tg];
                bh[ni][1] = Bh[(cb + g) * PSTR + pbase + tg + 4];
                bl[ni][0] = Bl[(cb + g) * PSTR + pbase + tg];
                bl[ni][1] = Bl[(cb + g) * PSTR + pbase + tg + 4];
            }
            #pragma unroll
            for (int mi = 0; mi < 4; mi++)
                #pragma unroll
                for (int ni = 0; ni < 2; ni++) {
                    float* c = acc[mi][ni];
                    mma16(c, ah[mi], bh[ni][0], bh[ni][1]);
                    mma16(c, ah[mi], bl[ni][0], bl[ni][1]);
                    mma16(c, al[mi], bh[ni][0], bh[ni][1]);
                }
        }
    }

    #pragma unroll
    for (int mi = 0; mi < 4; mi++) {
        int r0 = row0 + wm * 64 + mi * 16 + g;
        #pragma unroll
        for (int ni = 0; ni < 2; ni++) {
            int c = col0 + wn * 16 + ni * 8 + 2 * tg;
            float b0 = bias[c], b1 = bias[c + 1];
            *reinterpret_cast<float2*>(&g_qkv[(size_t)r0       * FQKV + c]) =
                make_float2(acc[mi][ni][0] + b0, acc[mi][ni][1] + b1);
            *reinterpret_cast<float2*>(&g_qkv[(size_t)(r0 + 8) * FQKV + c]) =
                make_float2(acc[mi][ni][2] + b0, acc[mi][ni][3] + b1);
        }
    }
}

// ===========================================================================
// Output projection: plain tf32 (unchanged from R4, 99us)
// ===========================================================================
__global__ void __launch_bounds__(256) k_out(const float* __restrict__ w,
                                             const float* __restrict__ bias,
                                             float* __restrict__ out)
{
    extern __shared__ uint32_t smo[];
    uint32_t* Ah = smo;            // 128*36
    uint32_t* Bh = Ah + 128 * 36;  // 64*36

    const int row0 = blockIdx.y * 128, col0 = blockIdx.x * 64;
    const int t = threadIdx.x, warp = t >> 5, lane = t & 31;
    const int wm = warp >> 2, wn = warp & 3;
    const int g = lane >> 2, tg = lane & 3;

    float acc[4][2][4] = {};
    float4 pa[4], pb[2];

    #pragma unroll
    for (int i = 0; i < 4; i++) {
        int idx = t + i * 256;
        int r = idx >> 3, c4 = (idx & 7) * 4;
        pa[i] = *reinterpret_cast<const float4*>(&g_oh[(size_t)(row0 + r) * EMB + c4]);
    }
    #pragma unroll
    for (int i = 0; i < 2; i++) {
        int idx = t + i * 256;
        int r = idx >> 3, c4 = (idx & 7) * 4;
        pb[i] = *reinterpret_cast<const float4*>(&w[(size_t)(col0 + r) * EMB + c4]);
    }

    for (int k0 = 0; k0 < EMB; k0 += 32) {
        __syncthreads();
        #pragma unroll
        for (int i = 0; i < 4; i++) {
            int idx = t + i * 256;
            int r = idx >> 3, c4 = (idx & 7) * 4;
            Ah[r * 36 + c4 + 0] = f2tf(pa[i].x); Ah[r * 36 + c4 + 1] = f2tf(pa[i].y);
            Ah[r * 36 + c4 + 2] = f2tf(pa[i].z); Ah[r * 36 + c4 + 3] = f2tf(pa[i].w);
        }
        #pragma unroll
        for (int i = 0; i < 2; i++) {
            int idx = t + i * 256;
            int r = idx >> 3, c4 = (idx & 7) * 4;
            Bh[r * 36 + c4 + 0] = f2tf(pb[i].x); Bh[r * 36 + c4 + 1] = f2tf(pb[i].y);
            Bh[r * 36 + c4 + 2] = f2tf(pb[i].z); Bh[r * 36 + c4 + 3] = f2tf(pb[i].w);
        }
        __syncthreads();

        int kn = k0 + 32;
        if (kn < EMB) {
            #pragma unroll
            for (int i = 0; i < 4; i++) {
                int idx = t + i * 256;
                int r = idx >> 3, c4 = (idx & 7) * 4;
                pa[i] = *reinterpret_cast<const float4*>(&g_oh[(size_t)(row0 + r) * EMB + kn + c4]);
            }
            #pragma unroll
            for (int i = 0; i < 2; i++) {
                int idx = t + i * 256;
                int r = idx >> 3, c4 = (idx & 7) * 4;
                pb[i] = *reinterpret_cast<const float4*>(&w[(size_t)(col0 + r) * EMB + kn + c4]);
            }
        }

        #pragma unroll
        for (int ks = 0; ks < 4; ks++) {
            const int kb = ks * 8;
            uint32_t ah[4][4], bh[2][2];
            #pragma unroll
            for (int mi = 0; mi < 4; mi++) {
                int rb = wm * 64 + mi * 16;
                ah[mi][0] = Ah[(rb + g    ) * 36 + kb + tg];
                ah[mi][1] = Ah[(rb + g + 8) * 36 + kb + tg];
                ah[mi][2] = Ah[(rb + g    ) * 36 + kb + tg + 4];
                ah[mi][3] = Ah[(rb + g + 8) * 36 + kb + tg + 4];
            }
            #pragma unroll
            for (int ni = 0; ni < 2; ni++) {
                int cb = wn * 16 + ni * 8;
                bh[ni][0] = Bh[(cb + g) * 36 + kb + tg];
                bh[ni][1] = Bh[(cb + g) * 36 + kb + tg + 4];
            }
            #pragma unroll
            for (int mi = 0; mi < 4; mi++)
                #pragma unroll
                for (int ni = 0; ni < 2; ni++)
                    mma8(acc[mi][ni], ah[mi][0], ah[mi][1], ah[mi][2], ah[mi][3],
                         bh[ni][0], bh[ni][1]);
        }
    }

    #pragma unroll
    for (int mi = 0; mi < 4; mi++) {
        int r0 = row0 + wm * 64 + mi * 16 + g;
        #pragma unroll
        for (int ni = 0; ni < 2; ni++) {
            int c = col0 + wn * 16 + ni * 8 + 2 * tg;
            float b0 = bias[c], b1 = bias[c + 1];
            *reinterpret_cast<float2*>(&out[(size_t)r0       * EMB + c]) =
                make_float2(acc[mi][ni][0] + b0, acc[mi][ni][1] + b1);
            *reinterpret_cast<float2*>(&out[(size_t)(r0 + 8) * EMB + c]) =
                make_float2(acc[mi][ni][2] + b0, acc[mi][ni][3] + b1);
        }
    }
}

// ===========================================================================
// Fully fused attention: CTA = 32 query rows of one (b,h).
//   QK^T (plain tf32, Q pinned in regs, K double-buffered) -> S in smem
//   softmax in smem -> attn probs written to gmem ONCE
//   P (tf32 bits in smem) @ V (double-buffered) -> g_oh
// smem = 32*1032*4 + 2*64*68*4 = 166912 B
// ===========================================================================
#define SSTR 1032
#define KSTR 68
#define VSTR 65

__device__ __forceinline__ void load_tile_regs(const float* __restrict__ Gp,
                                               int r0, int t, float4* r4)
{
    #pragma unroll
    for (int i = 0; i < 4; i++) {
        int idx = t + i * 256;
        int r = idx >> 4, c4 = (idx & 15) * 4;
        r4[i] = *reinterpret_cast<const float4*>(&Gp[(size_t)(r0 + r) * FQKV + c4]);
    }
}

// K: store [n][k] direct (row-major, stride KSTR)
__device__ __forceinline__ void store_k_smem(uint32_t* __restrict__ Kb,
                                             int t, const float4* r4)
{
    #pragma unroll
    for (int i = 0; i < 4; i++) {
        int idx = t + i * 256;
        int r = idx >> 4, c4 = (idx & 15) * 4;
        Kb[r * KSTR + c4 + 0] = f2tf(r4[i].x);
        Kb[r * KSTR + c4 + 1] = f2tf(r4[i].y);
        Kb[r * KSTR + c4 + 2] = f2tf(r4[i].z);
        Kb[r * KSTR + c4 + 3] = f2tf(r4[i].w);
    }
}

// V: store transposed [n][k] (stride VSTR)
__device__ __forceinline__ void store_v_smem(uint32_t* __restrict__ Vb,
                                             int t, const float4* r4)
{
    #pragma unroll
    for (int i = 0; i < 4; i++) {
        int idx = t + i * 256;
        int r = idx >> 4, c4 = (idx & 15) * 4;
        Vb[(c4 + 0) * VSTR + r] = f2tf(r4[i].x);
        Vb[(c4 + 1) * VSTR + r] = f2tf(r4[i].y);
        Vb[(c4 + 2) * VSTR + r] = f2tf(r4[i].z);
        Vb[(c4 + 3) * VSTR + r] = f2tf(r4[i].w);
    }
}

__global__ void __launch_bounds__(256) k_attn(float* __restrict__ attn)
{
    extern __shared__ float sm[];
    float*    S   = sm;                                 // 32*SSTR
    uint32_t* KV0 = (uint32_t*)(sm + 32 * SSTR);        // 64*KSTR
    uint32_t* KV1 = KV0 + 64 * KSTR;

    const int bh = blockIdx.y;
    const int bb = bh / NHEAD, h = bh % NHEAD;
    const int row0 = blockIdx.x * 32;
    const int t = threadIdx.x, warp = t >> 5, lane = t & 31;
    const int g = lane >> 2, tg = lane & 3;
    const int wm = warp >> 2, wn = warp & 3;

    const float* Qg = g_qkv + ((size_t)bb * SEQ + row0) * FQKV + h * HDIM;
    const float* Kg = g_qkv + (size_t)bb * SEQ * FQKV + EMB     + h * HDIM;
    const float* Vg = g_qkv + (size_t)bb * SEQ * FQKV + 2 * EMB + h * HDIM;
    float* Sg = attn + ((size_t)bh * SEQ + row0) * SEQ;

    // ---- stage Q (32x64) through KV0 as fp32, pin fragments in regs ----
    {
        float* Qs = (float*)KV0;
        #pragma unroll
        for (int i = 0; i < 2; i++) {
            int idx = t + i * 256;
            int r = idx >> 4, c4 = (idx & 15) * 4;
            float4 v = *reinterpret_cast<const float4*>(&Qg[(size_t)r * FQKV + c4]);
            Qs[r * KSTR + c4 + 0] = v.x; Qs[r * KSTR + c4 + 1] = v.y;
            Qs[r * KSTR + c4 + 2] = v.z; Qs[r * KSTR + c4 + 3] = v.w;
        }
    }
    __syncthreads();
    uint32_t qf[8][4];
    {
        const float* Qs = (const float*)KV0;
        const int rb = wm * 16;
        #pragma unroll
        for (int ks = 0; ks < 8; ks++) {
            int kb = ks * 8;
            qf[ks][0] = f2tf(Qs[(rb + g    ) * KSTR + kb + tg]);
            qf[ks][1] = f2tf(Qs[(rb + g + 8) * KSTR + kb + tg]);
            qf[ks][2] = f2tf(Qs[(rb + g    ) * KSTR + kb + tg + 4]);
            qf[ks][3] = f2tf(Qs[(rb + g + 8) * KSTR + kb + tg + 4]);
        }
    }
    __syncthreads();   // everyone done reading Q from KV0

    // ---- QK^T: 16 strips of 64 keys, double-buffered ----
    float4 kr[4];
    load_tile_regs(Kg, 0, t, kr);
    store_k_smem(KV0, t, kr);

    for (int s = 0; s < 16; s++) {
        if (s < 15) load_tile_regs(Kg, (s + 1) * 64, t, kr);
        __syncthreads();
        const uint32_t* Kb = (s & 1) ? KV1 : KV0;
        float acc[2][4] = {};
        #pragma unroll
        for (int ks = 0; ks < 8; ks++) {
            const int kb = ks * 8;
            #pragma unroll
            for (int ni = 0; ni < 2; ni++) {
                int cb = wn * 16 + ni * 8;
                uint32_t b0 = Kb[(cb + g) * KSTR + kb + tg];
                uint32_t b1 = Kb[(cb + g) * KSTR + kb + tg + 4];
                mma8(acc[ni], qf[ks][0], qf[ks][1], qf[ks][2], qf[ks][3], b0, b1);
            }
        }
        {
            int r = wm * 16 + g;
            #pragma unroll
            for (int ni = 0; ni < 2; ni++) {
                int c = s * 64 + wn * 16 + ni * 8 + 2 * tg;
                S[(size_t)r       * SSTR + c]     = acc[ni][0] * 0.125f;
                S[(size_t)r       * SSTR + c + 1] = acc[ni][1] * 0.125f;
                S[(size_t)(r + 8) * SSTR + c]     = acc[ni][2] * 0.125f;
                S[(size_t)(r + 8) * SSTR + c + 1] = acc[ni][3] * 0.125f;
            }
        }
        if (s < 15) store_k_smem((s & 1) ? KV0 : KV1, t, kr);
    }
    __syncthreads();

    // ---- softmax per row (4 rows/warp); write probs; restore tf32 bits ----
    #pragma unroll
    for (int j = 0; j < 4; j++) {
        int r = warp + j * 8;
        float* Sr = S + (size_t)r * SSTR;

        float m = -1e30f;
        #pragma unroll
        for (int it = 0; it < 8; it++) {
            float4 v = *reinterpret_cast<float4*>(&Sr[(it * 32 + lane) * 4]);
            m = fmaxf(m, fmaxf(fmaxf(v.x, v.y), fmaxf(v.z, v.w)));
        }
        #pragma unroll
        for (int o = 16; o > 0; o >>= 1) m = fmaxf(m, __shfl_xor_sync(0xffffffffu, m, o));

        float s = 0.0f;
        #pragma unroll
        for (int it = 0; it < 8; it++) {
            float4 v = *reinterpret_cast<float4*>(&Sr[(it * 32 + lane) * 4]);
            v.x = __expf(v.x - m); v.y = __expf(v.y - m);
            v.z = __expf(v.z - m); v.w = __expf(v.w - m);
            s += v.x + v.y + v.z + v.w;
            *reinterpret_cast<float4*>(&Sr[(it * 32 + lane) * 4]) = v;
        }
        #pragma unroll
        for (int o = 16; o > 0; o >>= 1) s += __shfl_xor_sync(0xffffffffu, s, o);
        float inv = 1.0f / s;

        float* arow = Sg + (size_t)r * SEQ;
        #pragma unroll
        for (int it = 0; it < 8; it++) {
            float4 v = *reinterpret_cast<float4*>(&Sr[(it * 32 + lane) * 4]);
            v.x *= inv; v.y *= inv; v.z *= inv; v.w *= inv;
            *reinterpret_cast<float4*>(&arow[(it * 32 + lane) * 4]) = v;
            uint4 u = make_uint4(f2tf(v.x), f2tf(v.y), f2tf(v.z), f2tf(v.w));
            *reinterpret_cast<uint4*>(&Sr[(it * 32 + lane) * 4]) = u;
        }
    }

    // ---- PV: O(32x64) = P @ V, double-buffered V (transposed smem) ----
    const uint32_t* Pt = (const uint32_t*)S;
    float4 vr[4];
    float acc2[2][4] = {};

    load_tile_regs(Vg, 0, t, vr);
    __syncthreads();               // P bits visible; QK/K buffers fully retired
    store_v_smem(KV0, t, vr);

    for (int s = 0; s < 16; s++) {
        if (s < 15) load_tile_regs(Vg, (s + 1) * 64, t, vr);
        __syncthreads();
        const uint32_t* Vb = (s & 1) ? KV1 : KV0;
        const int k0 = s * 64;
        #pragma unroll
        for (int ks = 0; ks < 8; ks++) {
            const int kb = ks * 8;
            uint32_t b0 = Vb[(warp * 8 + g) * VSTR + kb + tg];
            uint32_t b1 = Vb[(warp * 8 + g) * VSTR + kb + tg + 4];
            #pragma unroll
            for (int mi = 0; mi < 2; mi++) {
                uint32_t a0 = Pt[(size_t)(mi * 16 + g    ) * SSTR + k0 + kb + tg];
                uint32_t a1 = Pt[(size_t)(mi * 16 + g + 8) * SSTR + k0 + kb + tg];
                uint32_t a2 = Pt[(size_t)(mi * 16 + g    ) * SSTR + k0 + kb + tg + 4];
                uint32_t a3 = Pt[(size_t)(mi * 16 + g + 8) * SSTR + k0 + kb + tg + 4];
                mma8(acc2[mi], a0, a1, a2, a3, b0, b1);
            }
        }
        if (s < 15) store_v_smem((s & 1) ? KV0 : KV1, t, vr);
    }

    #pragma unroll
    for (int mi = 0; mi < 2; mi++) {
        int r = row0 + mi * 16 + g;
        int c = h * HDIM + warp * 8 + 2 * tg;
        *reinterpret_cast<float2*>(&g_oh[((size_t)bb * SEQ + r    ) * EMB + c]) =
            make_float2(acc2[mi][0], acc2[mi][1]);
        *reinterpret_cast<float2*>(&g_oh[((size_t)bb * SEQ + r + 8) * EMB + c]) =
            make_float2(acc2[mi][2], acc2[mi][3]);
    }
}

// ---------------------------------------------------------------------------
extern "C" void kernel_launch(void* const* d_in, const int* in_sizes, int n_in,
                              void* d_out, int out_size)
{
    const float* x     = (const float*)d_in[0];
    const float* w_qkv = (const float*)d_in[1];
    const float* b_qkv = (const float*)d_in[2];
    const float* w_out = (const float*)d_in[3];
    const float* b_out = (const float*)d_in[4];

    float* out  = (float*)d_out;
    float* attn = out + (size_t)MTOT * EMB;

    const int smem_qkv  = (2 * 128 * PSTR + 2 * 64 * PSTR) * 4;   // 30720
    const int smem_out  = (128 * 36 + 64 * 36) * 4;               // 27648
    const int smem_attn = (32 * SSTR + 2 * 64 * KSTR) * 4;        // 166912

    static bool attr_done = false;
    if (!attr_done) {
        cudaFuncSetAttribute(k_qkv,  cudaFuncAttributeMaxDynamicSharedMemorySize, smem_qkv);
        cudaFuncSetAttribute(k_out,  cudaFuncAttributeMaxDynamicSharedMemorySize, smem_out);
        cudaFuncSetAttribute(k_attn, cudaFuncAttributeMaxDynamicSharedMemorySize, smem_attn);
        attr_done = true;
    }

    k_qkv <<<dim3(FQKV / 64, MTOT / 128), 256, smem_qkv >>>(x, w_qkv, b_qkv);
    k_attn<<<dim3(SEQ / 32, BHTOT),       256, smem_attn>>>(attn);
    k_out <<<dim3(EMB / 64, MTOT / 128),  256, smem_out >>>(w_out, b_out, out);
}

// round 6
// speedup vs baseline: 2.1336x; 1.3036x over previous
#include <cuda_runtime.h>
#include <cuda_bf16.h>
#include <math.h>
#include <stdint.h>

#define EMB   768
#define NHEAD 12
#define HDIM  64
#define SEQ   1024
#define BATCH 8
#define MTOT  (BATCH * SEQ)
#define FQKV  (3 * EMB)
#define BHTOT (BATCH * NHEAD)

__device__ float g_qkv[(size_t)MTOT * FQKV];   // 75.5 MB
__device__ float g_oh [(size_t)MTOT * EMB];    // 25.2 MB

__device__ __forceinline__ uint32_t f2tf(float x) {
    uint32_t r;
    asm("cvt.rna.tf32.f32 %0, %1;" : "=r"(r) : "f"(x));
    return r;
}

__device__ __forceinline__ uint32_t smaddr(const void* p) {
    return (uint32_t)__cvta_generic_to_shared(p);
}

__device__ __forceinline__ void ldsm4(uint32_t* r, uint32_t a) {
    asm volatile("ldmatrix.sync.aligned.m8n8.x4.shared.b16 {%0,%1,%2,%3}, [%4];"
                 : "=r"(r[0]), "=r"(r[1]), "=r"(r[2]), "=r"(r[3]) : "r"(a));
}

__device__ __forceinline__ void mma8(float* c,
                                     uint32_t a0, uint32_t a1, uint32_t a2, uint32_t a3,
                                     uint32_t b0, uint32_t b1)
{
    asm volatile(
        "mma.sync.aligned.m16n8k8.row.col.f32.tf32.tf32.f32 "
        "{%0,%1,%2,%3}, {%4,%5,%6,%7}, {%8,%9}, {%0,%1,%2,%3};\n"
        : "+f"(c[0]), "+f"(c[1]), "+f"(c[2]), "+f"(c[3])
        : "r"(a0), "r"(a1), "r"(a2), "r"(a3), "r"(b0), "r"(b1));
}

__device__ __forceinline__ void mma16(float* c, const uint32_t* a,
                                      uint32_t b0, uint32_t b1)
{
    asm volatile(
        "mma.sync.aligned.m16n8k16.row.col.f32.bf16.bf16.f32 "
        "{%0,%1,%2,%3}, {%4,%5,%6,%7}, {%8,%9}, {%0,%1,%2,%3};\n"
        : "+f"(c[0]), "+f"(c[1]), "+f"(c[2]), "+f"(c[3])
        : "r"(a[0]), "r"(a[1]), "r"(a[2]), "r"(a[3]), "r"(b0), "r"(b1));
}

__device__ __forceinline__ void bf16_split2(float x, float y,
                                            uint32_t& hi, uint32_t& lo)
{
    __nv_bfloat162 h = __floats2bfloat162_rn(x, y);
    hi = *reinterpret_cast<uint32_t*>(&h);
    float rx = x - __bfloat162float(h.x);
    float ry = y - __bfloat162float(h.y);
    __nv_bfloat162 l = __floats2bfloat162_rn(rx, ry);
    lo = *reinterpret_cast<uint32_t*>(&l);
}

// ===========================================================================
// QKV projection: split-bf16, block 128x64, ldmatrix fragment loads.
// ===========================================================================
#define PSTR 20

__global__ void __launch_bounds__(256) k_qkv(const float* __restrict__ x,
                                             const float* __restrict__ w,
                                             const float* __restrict__ bias)
{
    extern __shared__ uint32_t smu[];
    uint32_t* Ah = smu;                // 128*PSTR ; Al follows contiguously
    uint32_t* Al = Ah + 128 * PSTR;
    uint32_t* Bh = Al + 128 * PSTR;    // 64*PSTR ; Bl follows
    uint32_t* Bl = Bh + 64 * PSTR;

    const int row0 = blockIdx.y * 128, col0 = blockIdx.x * 64;
    const int t = threadIdx.x, warp = t >> 5, lane = t & 31;
    const int wm = warp >> 2, wn = warp & 3;
    const int g = lane >> 2, tg = lane & 3;
    const int lr = lane & 15, lc = (lane >> 4) << 2;

    const uint32_t aAh = smaddr(Ah) + (uint32_t)((wm * 64 + lr) * PSTR + lc) * 4;
    const uint32_t aAl = aAh + 128 * PSTR * 4;
    const uint32_t aBh = smaddr(Bh) + (uint32_t)((wn * 16 + lr) * PSTR + lc) * 4;
    const uint32_t aBl = aBh + 64 * PSTR * 4;

    float acc[4][2][4] = {};
    float4 pa[4], pb[2];

    #pragma unroll
    for (int i = 0; i < 4; i++) {
        int idx = t + i * 256;
        int r = idx >> 3, c4 = (idx & 7) * 4;
        pa[i] = *reinterpret_cast<const float4*>(&x[(size_t)(row0 + r) * EMB + c4]);
    }
    #pragma unroll
    for (int i = 0; i < 2; i++) {
        int idx = t + i * 256;
        int r = idx >> 3, c4 = (idx & 7) * 4;
        pb[i] = *reinterpret_cast<const float4*>(&w[(size_t)(col0 + r) * EMB + c4]);
    }

    for (int k0 = 0; k0 < EMB; k0 += 32) {
        __syncthreads();
        #pragma unroll
        for (int i = 0; i < 4; i++) {
            int idx = t + i * 256;
            int r = idx >> 3, p0 = (idx & 7) * 2;
            uint32_t h0, l0, h1, l1;
            bf16_split2(pa[i].x, pa[i].y, h0, l0);
            bf16_split2(pa[i].z, pa[i].w, h1, l1);
            Ah[r * PSTR + p0] = h0; Ah[r * PSTR + p0 + 1] = h1;
            Al[r * PSTR + p0] = l0; Al[r * PSTR + p0 + 1] = l1;
        }
        #pragma unroll
        for (int i = 0; i < 2; i++) {
            int idx = t + i * 256;
            int r = idx >> 3, p0 = (idx & 7) * 2;
            uint32_t h0, l0, h1, l1;
            bf16_split2(pb[i].x, pb[i].y, h0, l0);
            bf16_split2(pb[i].z, pb[i].w, h1, l1);
            Bh[r * PSTR + p0] = h0; Bh[r * PSTR + p0 + 1] = h1;
            Bl[r * PSTR + p0] = l0; Bl[r * PSTR + p0 + 1] = l1;
        }
        __syncthreads();

        int kn = k0 + 32;
        if (kn < EMB) {
            #pragma unroll
            for (int i = 0; i < 4; i++) {
                int idx = t + i * 256;
                int r = idx >> 3, c4 = (idx & 7) * 4;
                pa[i] = *reinterpret_cast<const float4*>(&x[(size_t)(row0 + r) * EMB + kn + c4]);
            }
            #pragma unroll
            for (int i = 0; i < 2; i++) {
                int idx = t + i * 256;
                int r = idx >> 3, c4 = (idx & 7) * 4;
                pb[i] = *reinterpret_cast<const float4*>(&w[(size_t)(col0 + r) * EMB + kn + c4]);
            }
        }

        #pragma unroll
        for (int ks = 0; ks < 2; ks++) {
            const uint32_t po = (uint32_t)(ks * 8) * 4;
            uint32_t ah[4][4], al[4][4], bh[4], bl[4];
            #pragma unroll
            for (int mi = 0; mi < 4; mi++) {
                ldsm4(ah[mi], aAh + (uint32_t)(mi * 16 * PSTR) * 4 + po);
                ldsm4(al[mi], aAl + (uint32_t)(mi * 16 * PSTR) * 4 + po);
            }
            ldsm4(bh, aBh + po);
            ldsm4(bl, aBl + po);
            #pragma unroll
            for (int mi = 0; mi < 4; mi++)
                #pragma unroll
                for (int ni = 0; ni < 2; ni++) {
                    float* c = acc[mi][ni];
                    mma16(c, ah[mi], bh[ni], bh[2 + ni]);
                    mma16(c, ah[mi], bl[ni], bl[2 + ni]);
                    mma16(c, al[mi], bh[ni], bh[2 + ni]);
                }
        }
    }

    #pragma unroll
    for (int mi = 0; mi < 4; mi++) {
        int r0 = row0 + wm * 64 + mi * 16 + g;
        #pragma unroll
        for (int ni = 0; ni < 2; ni++) {
            int c = col0 + wn * 16 + ni * 8 + 2 * tg;
            float b0 = bias[c], b1 = bias[c + 1];
            *reinterpret_cast<float2*>(&g_qkv[(size_t)r0       * FQKV + c]) =
                make_float2(acc[mi][ni][0] + b0, acc[mi][ni][1] + b1);
            *reinterpret_cast<float2*>(&g_qkv[(size_t)(r0 + 8) * FQKV + c]) =
                make_float2(acc[mi][ni][2] + b0, acc[mi][ni][3] + b1);
        }
    }
}

// ===========================================================================
// Output projection: plain tf32, ldmatrix fragment loads.
// ===========================================================================
__global__ void __launch_bounds__(256) k_out(const float* __restrict__ w,
                                             const float* __restrict__ bias,
                                             float* __restrict__ out)
{
    extern __shared__ uint32_t smo[];
    uint32_t* Ah = smo;            // 128*36
    uint32_t* Bh = Ah + 128 * 36;  // 64*36

    const int row0 = blockIdx.y * 128, col0 = blockIdx.x * 64;
    const int t = threadIdx.x, warp = t >> 5, lane = t & 31;
    const int wm = warp >> 2, wn = warp & 3;
    const int g = lane >> 2, tg = lane & 3;
    const int lr = lane & 15, lc = (lane >> 4) << 2;

    const uint32_t aA = smaddr(Ah) + (uint32_t)((wm * 64 + lr) * 36 + lc) * 4;
    const uint32_t aB = smaddr(Bh) + (uint32_t)((wn * 16 + lr) * 36 + lc) * 4;

    float acc[4][2][4] = {};
    float4 pa[4], pb[2];

    #pragma unroll
    for (int i = 0; i < 4; i++) {
        int idx = t + i * 256;
        int r = idx >> 3, c4 = (idx & 7) * 4;
        pa[i] = *reinterpret_cast<const float4*>(&g_oh[(size_t)(row0 + r) * EMB + c4]);
    }
    #pragma unroll
    for (int i = 0; i < 2; i++) {
        int idx = t + i * 256;
        int r = idx >> 3, c4 = (idx & 7) * 4;
        pb[i] = *reinterpret_cast<const float4*>(&w[(size_t)(col0 + r) * EMB + c4]);
    }

    for (int k0 = 0; k0 < EMB; k0 += 32) {
        __syncthreads();
        #pragma unroll
        for (int i = 0; i < 4; i++) {
            int idx = t + i * 256;
            int r = idx >> 3, c4 = (idx & 7) * 4;
            Ah[r * 36 + c4 + 0] = f2tf(pa[i].x); Ah[r * 36 + c4 + 1] = f2tf(pa[i].y);
            Ah[r * 36 + c4 + 2] = f2tf(pa[i].z); Ah[r * 36 + c4 + 3] = f2tf(pa[i].w);
        }
        #pragma unroll
        for (int i = 0; i < 2; i++) {
            int idx = t + i * 256;
            int r = idx >> 3, c4 = (idx & 7) * 4;
            Bh[r * 36 + c4 + 0] = f2tf(pb[i].x); Bh[r * 36 + c4 + 1] = f2tf(pb[i].y);
            Bh[r * 36 + c4 + 2] = f2tf(pb[i].z); Bh[r * 36 + c4 + 3] = f2tf(pb[i].w);
        }
        __syncthreads();

        int kn = k0 + 32;
        if (kn < EMB) {
            #pragma unroll
            for (int i = 0; i < 4; i++) {
                int idx = t + i * 256;
                int r = idx >> 3, c4 = (idx & 7) * 4;
                pa[i] = *reinterpret_cast<const float4*>(&g_oh[(size_t)(row0 + r) * EMB + kn + c4]);
            }
            #pragma unroll
            for (int i = 0; i < 2; i++) {
                int idx = t + i * 256;
                int r = idx >> 3, c4 = (idx & 7) * 4;
                pb[i] = *reinterpret_cast<const float4*>(&w[(size_t)(col0 + r) * EMB + kn + c4]);
            }
        }

        #pragma unroll
        for (int ks = 0; ks < 4; ks++) {
            const uint32_t ko = (uint32_t)(ks * 8) * 4;
            uint32_t a[4][4], b[4];
            #pragma unroll
            for (int mi = 0; mi < 4; mi++)
                ldsm4(a[mi], aA + (uint32_t)(mi * 16 * 36) * 4 + ko);
            ldsm4(b, aB + ko);
            #pragma unroll
            for (int mi = 0; mi < 4; mi++)
                #pragma unroll
                for (int ni = 0; ni < 2; ni++)
                    mma8(acc[mi][ni], a[mi][0], a[mi][1], a[mi][2], a[mi][3],
                         b[ni], b[2 + ni]);
        }
    }

    #pragma unroll
    for (int mi = 0; mi < 4; mi++) {
        int r0 = row0 + wm * 64 + mi * 16 + g;
        #pragma unroll
        for (int ni = 0; ni < 2; ni++) {
            int c = col0 + wn * 16 + ni * 8 + 2 * tg;
            float b0 = bias[c], b1 = bias[c + 1];
            *reinterpret_cast<float2*>(&out[(size_t)r0       * EMB + c]) =
                make_float2(acc[mi][ni][0] + b0, acc[mi][ni][1] + b1);
            *reinterpret_cast<float2*>(&out[(size_t)(r0 + 8) * EMB + c]) =
                make_float2(acc[mi][ni][2] + b0, acc[mi][ni][3] + b1);
        }
    }
}

// ===========================================================================
// Fused attention: CTA = 32 query rows of one (b,h).
// QK^T (tf32, Q pinned, K via cp.async 128-strips + ldmatrix) -> S smem
// softmax -> attn written once; P re-stored as tf32 bits
// PV (tf32, P via ldmatrix, V via cp.async [k][d] layout)
// smem = 32*1036*4 + 2*128*72*4 = 206336 B
// ===========================================================================
#define SSTR 1036
#define KST  68
#define VST  72

__device__ __forceinline__ void issue_strip(const float* __restrict__ gp,
                                            float* buf, int s, int t, int stride)
{
    #pragma unroll
    for (int i = 0; i < 8; i++) {
        int idx = t + i * 256;
        int r = idx >> 4, c4 = (idx & 15) * 4;
        uint32_t dst = smaddr(buf + r * stride + c4);
        const float* src = gp + (size_t)(s * 128 + r) * FQKV + c4;
        asm volatile("cp.async.cg.shared.global [%0], [%1], 16;" :: "r"(dst), "l"(src));
    }
    asm volatile("cp.async.commit_group;" ::: "memory");
}

__global__ void __launch_bounds__(256) k_attn(float* __restrict__ attn)
{
    extern __shared__ float sm[];
    float* S  = sm;                       // 32*SSTR
    float* T0 = sm + 32 * SSTR;           // 128*VST region
    float* T1 = T0 + 128 * VST;

    const int bh = blockIdx.y;
    const int bb = bh / NHEAD, h = bh % NHEAD;
    const int row0 = blockIdx.x * 32;
    const int t = threadIdx.x, warp = t >> 5, lane = t & 31;
    const int g = lane >> 2, tg = lane & 3;
    const int wm = warp >> 2, wn = warp & 3;
    const int lr = lane & 15, lc = (lane >> 4) << 2;

    const float* Qg = g_qkv + ((size_t)bb * SEQ + row0) * FQKV + h * HDIM;
    const float* Kg = g_qkv + (size_t)bb * SEQ * FQKV + EMB     + h * HDIM;
    const float* Vg = g_qkv + (size_t)bb * SEQ * FQKV + 2 * EMB + h * HDIM;
    float* Sg = attn + ((size_t)bh * SEQ + row0) * SEQ;

    // ---- stage Q (32x64) into S region, pin tf32 fragments in regs ----
    #pragma unroll
    for (int i = 0; i < 2; i++) {
        int idx = t + i * 256;
        int r = idx >> 4, c4 = (idx & 15) * 4;
        float4 v = *reinterpret_cast<const float4*>(&Qg[(size_t)r * FQKV + c4]);
        S[r * KST + c4 + 0] = v.x; S[r * KST + c4 + 1] = v.y;
        S[r * KST + c4 + 2] = v.z; S[r * KST + c4 + 3] = v.w;
    }
    __syncthreads();
    uint32_t qf[8][4];
    {
        const int rb = wm * 16;
        #pragma unroll
        for (int ks = 0; ks < 8; ks++) {
            int kb = ks * 8;
            qf[ks][0] = f2tf(S[(rb + g    ) * KST + kb + tg]);
            qf[ks][1] = f2tf(S[(rb + g + 8) * KST + kb + tg]);
            qf[ks][2] = f2tf(S[(rb + g    ) * KST + kb + tg + 4]);
            qf[ks][3] = f2tf(S[(rb + g + 8) * KST + kb + tg + 4]);
        }
    }

    // ---- QK^T: 8 strips of 128 keys, cp.async double-buffered ----
    issue_strip(Kg, T0, 0, t, KST);
    const uint32_t kfragoff = (uint32_t)((wn * 32 + lr) * KST + lc) * 4;

    for (int s = 0; s < 8; s++) {
        if (s < 7) {
            issue_strip(Kg, (s & 1) ? T0 : T1, s + 1, t, KST);
            asm volatile("cp.async.wait_group 1;" ::: "memory");
        } else {
            asm volatile("cp.async.wait_group 0;" ::: "memory");
        }
        __syncthreads();
        const float* Kb = (s & 1) ? T1 : T0;
        const uint32_t kbase = smaddr(Kb) + kfragoff;

        float acc[4][4] = {};
        #pragma unroll
        for (int ks = 0; ks < 8; ks++) {
            uint32_t b0[4], b1[4];
            ldsm4(b0, kbase + (uint32_t)(ks * 8) * 4);
            ldsm4(b1, kbase + (uint32_t)(16 * KST + ks * 8) * 4);
            mma8(acc[0], qf[ks][0], qf[ks][1], qf[ks][2], qf[ks][3], b0[0], b0[2]);
            mma8(acc[1], qf[ks][0], qf[ks][1], qf[ks][2], qf[ks][3], b0[1], b0[3]);
            mma8(acc[2], qf[ks][0], qf[ks][1], qf[ks][2], qf[ks][3], b1[0], b1[2]);
            mma8(acc[3], qf[ks][0], qf[ks][1], qf[ks][2], qf[ks][3], b1[1], b1[3]);
        }
        {
            int r = wm * 16 + g;
            #pragma unroll
            for (int ni = 0; ni < 4; ni++) {
                int c = s * 128 + wn * 32 + ni * 8 + 2 * tg;
                S[(size_t)r       * SSTR + c]     = acc[ni][0] * 0.125f;
                S[(size_t)r       * SSTR + c + 1] = acc[ni][1] * 0.125f;
                S[(size_t)(r + 8) * SSTR + c]     = acc[ni][2] * 0.125f;
                S[(size_t)(r + 8) * SSTR + c + 1] = acc[ni][3] * 0.125f;
            }
        }
        __syncthreads();   // retire buffer before producer overwrite next round
    }

    // prefetch V strip 0 under softmax (T0 free: last K strip used T1)
    issue_strip(Vg, T0, 0, t, VST);

    // ---- softmax per row (4 rows/warp); write probs; restore tf32 bits ----
    #pragma unroll
    for (int j = 0; j < 4; j++) {
        int r = warp + j * 8;
        float* Sr = S + (size_t)r * SSTR;

        float m = -1e30f;
        #pragma unroll
        for (int it = 0; it < 8; it++) {
            float4 v = *reinterpret_cast<float4*>(&Sr[(it * 32 + lane) * 4]);
            m = fmaxf(m, fmaxf(fmaxf(v.x, v.y), fmaxf(v.z, v.w)));
        }
        #pragma unroll
        for (int o = 16; o > 0; o >>= 1) m = fmaxf(m, __shfl_xor_sync(0xffffffffu, m, o));

        float sum = 0.0f;
        #pragma unroll
        for (int it = 0; it < 8; it++) {
            float4 v = *reinterpret_cast<float4*>(&Sr[(it * 32 + lane) * 4]);
            v.x = __expf(v.x - m); v.y = __expf(v.y - m);
            v.z = __expf(v.z - m); v.w = __expf(v.w - m);
            sum += v.x + v.y + v.z + v.w;
            *reinterpret_cast<float4*>(&Sr[(it * 32 + lane) * 4]) = v;
        }
        #pragma unroll
        for (int o = 16; o > 0; o >>= 1) sum += __shfl_xor_sync(0xffffffffu, sum, o);
        float inv = 1.0f / sum;

        float* arow = Sg + (size_t)r * SEQ;
        #pragma unroll
        for (int it = 0; it < 8; it++) {
            float4 v = *reinterpret_cast<float4*>(&Sr[(it * 32 + lane) * 4]);
            v.x *= inv; v.y *= inv; v.z *= inv; v.w *= inv;
            *reinterpret_cast<float4*>(&arow[(it * 32 + lane) * 4]) = v;
            uint4 u = make_uint4(f2tf(v.x), f2tf(v.y), f2tf(v.z), f2tf(v.w));
            *reinterpret_cast<uint4*>(&Sr[(it * 32 + lane) * 4]) = u;
        }
    }

    // ---- PV: 8 strips of 128, P via ldmatrix from S, V from [k][d] smem ----
    const uint32_t pbase0 = smaddr(S) + (uint32_t)(lr * SSTR + lc) * 4;
    float acc2[2][4] = {};

    for (int s = 0; s < 8; s++) {
        if (s < 7) {
            issue_strip(Vg, (s & 1) ? T0 : T1, s + 1, t, VST);
            asm volatile("cp.async.wait_group 1;" ::: "memory");
        } else {
            asm volatile("cp.async.wait_group 0;" ::: "memory");
        }
        __syncthreads();   // also orders softmax P-writes before first P reads
        const float* Vb = (s & 1) ? T1 : T0;
        const uint32_t* Vu = (const uint32_t*)Vb;
        const int vc = warp * 8 + g;

        #pragma unroll
        for (int ks = 0; ks < 16; ks++) {
            const int kb = ks * 8;
            uint32_t a0[4], a1[4];
            ldsm4(a0, pbase0 + (uint32_t)(s * 128 + kb) * 4);
            ldsm4(a1, pbase0 + (uint32_t)(16 * SSTR + s * 128 + kb) * 4);
            uint32_t b0 = Vu[(kb + tg    ) * VST + vc];
            uint32_t b1 = Vu[(kb + tg + 4) * VST + vc];
            mma8(acc2[0], a0[0], a0[1], a0[2], a0[3], b0, b1);
            mma8(acc2[1], a1[0], a1[1], a1[2], a1[3], b0, b1);
        }
        __syncthreads();
    }

    #pragma unroll
    for (int mi = 0; mi < 2; mi++) {
        int r = row0 + mi * 16 + g;
        int c = h * HDIM + warp * 8 + 2 * tg;
        *reinterpret_cast<float2*>(&g_oh[((size_t)bb * SEQ + r    ) * EMB + c]) =
            make_float2(acc2[mi][0], acc2[mi][1]);
        *reinterpret_cast<float2*>(&g_oh[((size_t)bb * SEQ + r + 8) * EMB + c]) =
            make_float2(acc2[mi][2], acc2[mi][3]);
    }
}

// ---------------------------------------------------------------------------
extern "C" void kernel_launch(void* const* d_in, const int* in_sizes, int n_in,
                              void* d_out, int out_size)
{
    const float* x     = (const float*)d_in[0];
    const float* w_qkv = (const float*)d_in[1];
    const float* b_qkv = (const float*)d_in[2];
    const float* w_out = (const float*)d_in[3];
    const float* b_out = (const float*)d_in[4];

    float* out  = (float*)d_out;
    float* attn = out + (size_t)MTOT * EMB;

    const int smem_qkv  = (2 * 128 * PSTR + 2 * 64 * PSTR) * 4;   // 30720
    const int smem_out  = (128 * 36 + 64 * 36) * 4;               // 27648
    const int smem_attn = (32 * SSTR + 2 * 128 * VST) * 4;        // 206336

    static bool attr_done = false;
    if (!attr_done) {
        cudaFuncSetAttribute(k_qkv,  cudaFuncAttributeMaxDynamicSharedMemorySize, smem_qkv);
        cudaFuncSetAttribute(k_out,  cudaFuncAttributeMaxDynamicSharedMemorySize, smem_out);
        cudaFuncSetAttribute(k_attn, cudaFuncAttributeMaxDynamicSharedMemorySize, smem_attn);
        attr_done = true;
    }

    k_qkv <<<dim3(FQKV / 64, MTOT / 128), 256, smem_qkv >>>(x, w_qkv, b_qkv);
    k_attn<<<dim3(SEQ / 32, BHTOT),       256, smem_attn>>>(attn);
    k_out <<<dim3(EMB / 64, MTOT / 128),  256, smem_out >>>(w_out, b_out, out);
}